// round 14
// baseline (speedup 1.0000x reference)
#include <cuda_runtime.h>
#include <cuda_fp16.h>
#include <math.h>
#include <stdint.h>

#define N_MAX 500000
#define B_MAX 10000
#define D 256

// ---------------- scratch (static device globals; no runtime alloc) --------
__device__ float g_gate[N_MAX];
__device__ float g_alpha[N_MAX];
__device__ int   g_batch32[N_MAX];
__device__ int   g_segstart[B_MAX + 1];
__device__ float g_xg[(size_t)B_MAX * D];
__device__ int   g_is64;
__device__ __half g_xhi[(size_t)N_MAX * D];
__device__ __half g_WhiT[D * D];                 // [n][k]
__device__ __half g_catA[(size_t)B_MAX * 2 * D]; // [g][ xg | xg_old ] fp16
__device__ __half g_WtT[2 * D * D];              // [n][k2], k2 = 512

// ---------------- helpers ----------------------------------------------------
__device__ __forceinline__ uint32_t smem_u32(const void* p) {
    uint32_t a;
    asm("{ .reg .u64 t; cvta.to.shared.u64 t, %1; cvt.u32.u64 %0, t; }"
        : "=r"(a) : "l"(p));
    return a;
}

#define LDSM_X4(r0, r1, r2, r3, addr) \
    asm volatile("ldmatrix.sync.aligned.m8n8.x4.shared.b16 {%0,%1,%2,%3}, [%4];" \
                 : "=r"(r0), "=r"(r1), "=r"(r2), "=r"(r3) : "r"(addr))

#define MMA16816(c0, c1, c2, c3, a0, a1, a2, a3, b0, b1) \
    asm volatile("mma.sync.aligned.m16n8k16.row.col.f32.f16.f16.f32 " \
                 "{%0,%1,%2,%3}, {%4,%5,%6,%7}, {%8,%9}, {%0,%1,%2,%3};" \
                 : "+f"(c0), "+f"(c1), "+f"(c2), "+f"(c3) \
                 : "r"(a0), "r"(a1), "r"(a2), "r"(a3), "r"(b0), "r"(b1))

#define CP16(dst, src) \
    asm volatile("cp.async.cg.shared.global [%0], [%1], 16;" \
                 :: "r"(dst), "l"(src) : "memory")
#define CP_COMMIT() asm volatile("cp.async.commit_group;" ::: "memory")
#define CP_WAIT(nn)  asm volatile("cp.async.wait_group %0;" :: "n"(nn) : "memory")

__device__ __forceinline__ uint32_t pack_hi2(float x, float y) {
    __half2 h = __halves2half2(__float2half_rn(x), __float2half_rn(y));
    return *(uint32_t*)&h;
}

// ---------------- dtype detection for batch (int32 vs int64) ----------------
__global__ void k_detect(const void* __restrict__ batch, int n) {
    const unsigned long long* p = (const unsigned long long*)batch;
    unsigned long long v = 0;
    int half = n / 2;
    v |= p[half - 1];
    v |= p[half / 2];
    v |= p[half / 4];
    g_is64 = (v < 0x80000000ull) ? 1 : 0;
}

// ---------------- segment boundaries from sorted batch ----------------------
__global__ void k_seg(const void* __restrict__ batch, int n, int b) {
    int i = blockIdx.x * blockDim.x + threadIdx.x;
    if (i >= n) return;
    const int is64 = g_is64;
    int bi, prev;
    if (is64) {
        bi = (int)((const long long*)batch)[i];
        prev = (i == 0) ? -1 : (int)((const long long*)batch)[i - 1];
    } else {
        bi = ((const int*)batch)[i];
        prev = (i == 0) ? -1 : ((const int*)batch)[i - 1];
    }
    if (bi < 0) bi = 0;
    if (bi > b - 1) bi = b - 1;
    if (prev < -1) prev = -1;
    if (prev > b - 1) prev = b - 1;
    g_batch32[i] = bi;
    for (int bb = prev + 1; bb <= bi; ++bb) g_segstart[bb] = i;
    if (i == n - 1) {
        for (int bb = bi + 1; bb <= b; ++bb) g_segstart[bb] = n;
    }
}

// -------- gate = x @ W_gate + b_gate, fused with x -> fp16 (16B stores) -----
__global__ void k_gate(const float* __restrict__ x, const float* __restrict__ Wg,
                       const float* __restrict__ bg, int n) {
    int warp = (blockIdx.x * blockDim.x + threadIdx.x) >> 5;
    int lane = threadIdx.x & 31;
    if (warp >= n) return;
    const float4* xr = (const float4*)(x + (size_t)warp * D);
    const float4* wr = (const float4*)Wg;
    uint4* hr = (uint4*)(g_xhi + (size_t)warp * D);
    float4 a0 = xr[2 * lane], a1 = xr[2 * lane + 1];
    float4 w0 = wr[2 * lane], w1 = wr[2 * lane + 1];
    float acc = a0.x * w0.x + a0.y * w0.y + a0.z * w0.z + a0.w * w0.w +
                a1.x * w1.x + a1.y * w1.y + a1.z * w1.z + a1.w * w1.w;
    uint4 h;
    h.x = pack_hi2(a0.x, a0.y);
    h.y = pack_hi2(a0.z, a0.w);
    h.z = pack_hi2(a1.x, a1.y);
    h.w = pack_hi2(a1.z, a1.w);
    hr[lane] = h;
#pragma unroll
    for (int o = 16; o; o >>= 1) acc += __shfl_xor_sync(0xffffffffu, acc, o);
    if (lane == 0) g_gate[warp] = acc + bg[0];
}

// ------- W_feat -> WhiT [n][k] fp16  AND  W_t -> WtT [n][k2] fp16 -----------
__global__ void k_convW2(const float* __restrict__ Wf, const float* __restrict__ Wt) {
    int t = blockIdx.x * blockDim.x + threadIdx.x;
    if (t < D * D) {
        int nn = t >> 8, kk = t & 255;
        g_WhiT[nn * D + kk] = __float2half_rn(Wf[kk * D + nn]);
    } else if (t < 3 * D * D) {
        int u = t - D * D;
        int k2 = u >> 8, nn = u & 255;
        g_WtT[nn * 2 * D + k2] = __float2half_rn(Wt[k2 * D + nn]);
    }
}

// ---------------- [xg | xg_old] -> fp16 packed A ----------------------------
__global__ void k_convA(const float* __restrict__ xg_old, int b) {
    int t = blockIdx.x * blockDim.x + threadIdx.x;
    if (t >= b * D) return;
    int g = t >> 8, c = t & 255;
    g_catA[(size_t)g * 512 + c]       = __float2half_rn(g_xg[(size_t)g * D + c]);
    g_catA[(size_t)g * 512 + 256 + c] = __float2half_rn(xg_old[(size_t)g * D + c]);
}

// ---------------- per-graph softmax weights (warp per graph) ----------------
__global__ void k_alpha(int b) {
    int w = (blockIdx.x * blockDim.x + threadIdx.x) >> 5;
    int lane = threadIdx.x & 31;
    if (w >= b) return;
    int s = g_segstart[w], e = g_segstart[w + 1];
    if (s >= e) return;
    float m = -1e30f;
    for (int i = s + lane; i < e; i += 32) m = fmaxf(m, g_gate[i]);
#pragma unroll
    for (int o = 16; o; o >>= 1) m = fmaxf(m, __shfl_xor_sync(0xffffffffu, m, o));
    float sum = 0.f;
    for (int i = s + lane; i < e; i += 32) sum += expf(g_gate[i] - m);
#pragma unroll
    for (int o = 16; o; o >>= 1) sum += __shfl_xor_sync(0xffffffffu, sum, o);
    float inv = 1.0f / sum;
    for (int i = s + lane; i < e; i += 32) g_alpha[i] = expf(g_gate[i] - m) * inv;
}

// ---------------- zero xg accumulator ---------------------------------------
__global__ void k_zero(int total4) {
    int i = blockIdx.x * blockDim.x + threadIdx.x;
    if (i < total4) ((float4*)g_xg)[i] = make_float4(0.f, 0.f, 0.f, 0.f);
}

// ========= single-term fp16 GEMM: xg += alpha * lrelu(xhi @ Whi + b) ========
// CTA 128x128, 512 threads, 2 CTAs/SM. A and B chunk tiles (K=64) stream
// together through 2 cp.async stages; 4 chunks cover K=256.
#define LDKB 144                 // tile row stride bytes (64 halfs + pad)
#define TILE_B 18432             // one 128-row tile buffer
#define STG_B  36864             // stage = A tile + B tile
#define OFF_BATCH 73728
#define OFF_ALPHA 74240
#define OFF_BIAS  74752
#define SMEM_MAIN 75264
#define SD_STRIDE 130

__global__ void __launch_bounds__(512, 2)
k_main_mma(const float* __restrict__ bf, int n) {
    extern __shared__ char smem[];
    const int tid = threadIdx.x;
    const int m0 = blockIdx.y * 128;
    const int n0 = blockIdx.x * 128;
    const uint32_t sbase = smem_u32(smem);
    int*   sBatch = (int*)(smem + OFF_BATCH);
    float* sAlpha = (float*)(smem + OFF_ALPHA);
    float* sBias  = (float*)(smem + OFF_BIAS);
    float* sD     = (float*)smem;   // reused after compute (128 x 130 fp32)

    if (tid < 128) {
        int r = m0 + tid;
        sBatch[tid] = (r < n) ? g_batch32[r] : -1;
        sBias[tid]  = bf[n0 + tid];
    } else if (tid < 256) {
        int r = m0 + tid - 128;
        sAlpha[tid - 128] = (r < n) ? g_alpha[r] : 0.f;
    }

    const int crow = tid >> 2;
    const int cseg = tid & 3;
    const char* whiT = (const char*)g_WhiT;
    const char* xhi  = (const char*)g_xhi;

    const bool avalid = (m0 + crow) < n;
    const size_t asrc_row = ((size_t)(m0 + (avalid ? crow : 0))) * 512;
    const size_t bsrc_row = ((size_t)(n0 + crow)) * 512;
    const uint32_t cdstA = sbase + crow * LDKB;
    const uint32_t cdstB = sbase + TILE_B + crow * LDKB;

    // fill stage st with chunk ch (A + B tiles)
    auto fill = [&](int st, int ch) {
        const uint32_t so = (uint32_t)(st * STG_B);
        const size_t ko = (size_t)(ch * 128);
        if (avalid) {
#pragma unroll
            for (int j = 0; j < 2; j++) {
                int s = cseg + 4 * j;
                CP16(cdstA + so + s * 16, xhi + asrc_row + ko + s * 16);
            }
        } else {
#pragma unroll
            for (int j = 0; j < 2; j++) {
                int s = cseg + 4 * j;
                asm volatile("st.shared.v4.b32 [%0], {%1,%1,%1,%1};"
                             :: "r"(cdstA + so + s * 16), "r"(0u));
            }
        }
#pragma unroll
        for (int j = 0; j < 2; j++) {
            int s = cseg + 4 * j;
            CP16(cdstB + so + s * 16, whiT + bsrc_row + ko + s * 16);
        }
        CP_COMMIT();
    };

    fill(0, 0);
    fill(1, 1);
    CP_WAIT(1);
    __syncthreads();

    const int wid = tid >> 5, lane = tid & 31;
    const int wm = wid >> 2, wn = wid & 3;
    const uint32_t a_off = (uint32_t)((wm * 32 + (lane & 15)) * LDKB + ((lane >> 4) << 4));
    const uint32_t b_off = (uint32_t)((wn * 32 + (lane & 15)) * LDKB + ((lane >> 4) << 4)) + TILE_B;

    float c[2][4][4];
#pragma unroll
    for (int mi = 0; mi < 2; mi++)
#pragma unroll
        for (int nt = 0; nt < 4; nt++)
#pragma unroll
            for (int q = 0; q < 4; q++) c[mi][nt][q] = 0.f;

    for (int ch = 0; ch < 4; ch++) {
        const int st = ch & 1;
        const uint32_t aH = sbase + (uint32_t)(st * STG_B) + a_off;
        const uint32_t bH = sbase + (uint32_t)(st * STG_B) + b_off;
#pragma unroll
        for (int ks = 0; ks < 4; ks++) {
            const uint32_t koff = (uint32_t)(ks * 32);
            uint32_t ah[2][4], bh[2][4];
#pragma unroll
            for (int mi = 0; mi < 2; mi++) {
                uint32_t adr = aH + (uint32_t)(mi * 16 * LDKB) + koff;
                LDSM_X4(ah[mi][0], ah[mi][1], ah[mi][2], ah[mi][3], adr);
            }
#pragma unroll
            for (int np = 0; np < 2; np++) {
                uint32_t adr = bH + (uint32_t)(np * 16 * LDKB) + koff;
                LDSM_X4(bh[np][0], bh[np][1], bh[np][2], bh[np][3], adr);
            }
#pragma unroll
            for (int mi = 0; mi < 2; mi++)
#pragma unroll
                for (int np = 0; np < 2; np++)
#pragma unroll
                    for (int t = 0; t < 2; t++) {
                        float* cc = c[mi][np * 2 + t];
                        MMA16816(cc[0], cc[1], cc[2], cc[3],
                                 ah[mi][0], ah[mi][1], ah[mi][2], ah[mi][3],
                                 bh[np][t], bh[np][t + 2]);
                    }
        }
        __syncthreads();   // all warps done reading stage st

        if (ch + 2 < 4) fill(st, ch + 2);
        if (ch == 0 || ch == 1) {
            CP_WAIT(1);
            __syncthreads();
        } else if (ch == 2) {
            CP_WAIT(0);
            __syncthreads();
        }
    }

    // ---- epilogue: bias + lrelu + alpha -> sD ----
#pragma unroll
    for (int mi = 0; mi < 2; mi++) {
        const int r0 = wm * 32 + mi * 16 + (lane >> 2);
        const int r1 = r0 + 8;
        const float al0 = sAlpha[r0], al1 = sAlpha[r1];
#pragma unroll
        for (int nt = 0; nt < 4; nt++) {
            const int col = wn * 32 + nt * 8 + (lane & 3) * 2;
            const float b0 = sBias[col], b1 = sBias[col + 1];
            float v0 = c[mi][nt][0] + b0, v1 = c[mi][nt][1] + b1;
            float v2 = c[mi][nt][2] + b0, v3 = c[mi][nt][3] + b1;
            v0 = (v0 >= 0.f) ? v0 : 0.01f * v0;
            v1 = (v1 >= 0.f) ? v1 : 0.01f * v1;
            v2 = (v2 >= 0.f) ? v2 : 0.01f * v2;
            v3 = (v3 >= 0.f) ? v3 : 0.01f * v3;
            *(float2*)&sD[r0 * SD_STRIDE + col] = make_float2(v0 * al0, v1 * al0);
            *(float2*)&sD[r1 * SD_STRIDE + col] = make_float2(v2 * al1, v3 * al1);
        }
    }
    __syncthreads();

    // ---- run-length compressed segment reduction + atomics ----
    {
        const int col = tid & 127, q = tid >> 7;
        const int rbeg = q * 32;
        float sum = 0.f;
        int prevb = -2;
        for (int r = 0; r < 32; r++) {
            int rr = rbeg + r;
            int b = sBatch[rr];
            if (b != prevb) {
                if (prevb >= 0)
                    atomicAdd(&g_xg[(size_t)prevb * D + n0 + col], sum);
                sum = 0.f;
                prevb = b;
            }
            if (b >= 0) sum += sD[rr * SD_STRIDE + col];
        }
        if (prevb >= 0) atomicAdd(&g_xg[(size_t)prevb * D + n0 + col], sum);
    }
}

// ===== fp16 final GEMM: out = lrelu([xg|xg_old] @ W_t + b_t) + xg_old =======
// CTA 128x128, 512 threads, 2 CTAs/SM. A+B tiles stream together in 2 stages;
// 8 chunks cover K2=512.
#define F_OFF_BIAS 73728
#define SMEM_FIN   74240

__global__ void __launch_bounds__(512, 2)
k_final_mma(const float* __restrict__ xg_old, const float* __restrict__ bt,
            float* __restrict__ out, int bsz) {
    extern __shared__ char smem[];
    const int tid = threadIdx.x;
    const int m0 = blockIdx.y * 128;
    const int n0 = blockIdx.x * 128;
    const uint32_t sbase = smem_u32(smem);
    float* sBias = (float*)(smem + F_OFF_BIAS);

    if (tid < 128) sBias[tid] = bt[n0 + tid];

    const int crow = tid >> 2;
    const int cseg = tid & 3;
    const char* wt  = (const char*)g_WtT;
    const char* cat = (const char*)g_catA;

    const bool avalid = (m0 + crow) < bsz;
    const size_t asrc_row = ((size_t)(m0 + (avalid ? crow : 0))) * 1024;
    const size_t bsrc_row = ((size_t)(n0 + crow)) * 1024;
    const uint32_t cdstA = sbase + crow * LDKB;
    const uint32_t cdstB = sbase + TILE_B + crow * LDKB;

    auto fill = [&](int st, int ch) {
        const uint32_t so = (uint32_t)(st * STG_B);
        const size_t ko = (size_t)(ch * 128);
        if (avalid) {
#pragma unroll
            for (int j = 0; j < 2; j++) {
                int s = cseg + 4 * j;
                CP16(cdstA + so + s * 16, cat + asrc_row + ko + s * 16);
            }
        } else {
#pragma unroll
            for (int j = 0; j < 2; j++) {
                int s = cseg + 4 * j;
                asm volatile("st.shared.v4.b32 [%0], {%1,%1,%1,%1};"
                             :: "r"(cdstA + so + s * 16), "r"(0u));
            }
        }
#pragma unroll
        for (int j = 0; j < 2; j++) {
            int s = cseg + 4 * j;
            CP16(cdstB + so + s * 16, wt + bsrc_row + ko + s * 16);
        }
        CP_COMMIT();
    };

    fill(0, 0);
    fill(1, 1);
    CP_WAIT(1);
    __syncthreads();

    const int wid = tid >> 5, lane = tid & 31;
    const int wm = wid >> 2, wn = wid & 3;
    const uint32_t a_off = (uint32_t)((wm * 32 + (lane & 15)) * LDKB + ((lane >> 4) << 4));
    const uint32_t b_off = (uint32_t)((wn * 32 + (lane & 15)) * LDKB + ((lane >> 4) << 4)) + TILE_B;

    float c[2][4][4];
#pragma unroll
    for (int mi = 0; mi < 2; mi++)
#pragma unroll
        for (int nt = 0; nt < 4; nt++)
#pragma unroll
            for (int q = 0; q < 4; q++) c[mi][nt][q] = 0.f;

    for (int ch = 0; ch < 8; ch++) {
        const int st = ch & 1;
        const uint32_t aH = sbase + (uint32_t)(st * STG_B) + a_off;
        const uint32_t bH = sbase + (uint32_t)(st * STG_B) + b_off;
#pragma unroll
        for (int ks = 0; ks < 4; ks++) {
            const uint32_t koff = (uint32_t)(ks * 32);
            uint32_t ah[2][4], bh[2][4];
#pragma unroll
            for (int mi = 0; mi < 2; mi++) {
                uint32_t adr = aH + (uint32_t)(mi * 16 * LDKB) + koff;
                LDSM_X4(ah[mi][0], ah[mi][1], ah[mi][2], ah[mi][3], adr);
            }
#pragma unroll
            for (int np = 0; np < 2; np++) {
                uint32_t adr = bH + (uint32_t)(np * 16 * LDKB) + koff;
                LDSM_X4(bh[np][0], bh[np][1], bh[np][2], bh[np][3], adr);
            }
#pragma unroll
            for (int mi = 0; mi < 2; mi++)
#pragma unroll
                for (int np = 0; np < 2; np++)
#pragma unroll
                    for (int t = 0; t < 2; t++) {
                        float* cc = c[mi][np * 2 + t];
                        MMA16816(cc[0], cc[1], cc[2], cc[3],
                                 ah[mi][0], ah[mi][1], ah[mi][2], ah[mi][3],
                                 bh[np][t], bh[np][t + 2]);
                    }
        }
        __syncthreads();

        if (ch + 2 < 8) fill(st, ch + 2);
        if (ch < 6) {
            CP_WAIT(1);
            __syncthreads();
        } else if (ch == 6) {
            CP_WAIT(0);
            __syncthreads();
        }
    }

    // epilogue: bias + lrelu + residual, direct global write
#pragma unroll
    for (int mi = 0; mi < 2; mi++) {
        const int r0 = wm * 32 + mi * 16 + (lane >> 2);
        const int r1 = r0 + 8;
#pragma unroll
        for (int nt = 0; nt < 4; nt++) {
            const int col = wn * 32 + nt * 8 + (lane & 3) * 2;
            const float b0 = sBias[col], b1 = sBias[col + 1];
            int g0 = m0 + r0, g1 = m0 + r1;
            if (g0 < bsz) {
                float2 res = *(const float2*)(xg_old + (size_t)g0 * D + n0 + col);
                float v0 = c[mi][nt][0] + b0, v1 = c[mi][nt][1] + b1;
                v0 = (v0 >= 0.f) ? v0 : 0.01f * v0;
                v1 = (v1 >= 0.f) ? v1 : 0.01f * v1;
                *(float2*)(out + (size_t)g0 * D + n0 + col) =
                    make_float2(v0 + res.x, v1 + res.y);
            }
            if (g1 < bsz) {
                float2 res = *(const float2*)(xg_old + (size_t)g1 * D + n0 + col);
                float v2 = c[mi][nt][2] + b0, v3 = c[mi][nt][3] + b1;
                v2 = (v2 >= 0.f) ? v2 : 0.01f * v2;
                v3 = (v3 >= 0.f) ? v3 : 0.01f * v3;
                *(float2*)(out + (size_t)g1 * D + n0 + col) =
                    make_float2(v2 + res.x, v3 + res.y);
            }
        }
    }
}

// ---------------- launcher ---------------------------------------------------
extern "C" void kernel_launch(void* const* d_in, const int* in_sizes, int n_in,
                              void* d_out, int out_size) {
    const float* xg_old = (const float*)d_in[0];
    const float* x      = (const float*)d_in[1];
    const void*  batch  = d_in[2];
    const float* W_gate = (const float*)d_in[3];
    const float* b_gate = (const float*)d_in[4];
    const float* W_feat = (const float*)d_in[5];
    const float* b_feat = (const float*)d_in[6];
    const float* W_t    = (const float*)d_in[7];
    const float* b_t    = (const float*)d_in[8];
    float*       out    = (float*)d_out;

    int n = in_sizes[2];
    int b = in_sizes[0] / D;
    if (n > N_MAX) n = N_MAX;
    if (b > B_MAX) b = B_MAX;

    cudaFuncSetAttribute(k_main_mma, cudaFuncAttributeMaxDynamicSharedMemorySize,
                         SMEM_MAIN);
    cudaFuncSetAttribute(k_final_mma, cudaFuncAttributeMaxDynamicSharedMemorySize,
                         SMEM_FIN);

    k_detect<<<1, 1>>>(batch, n);
    k_seg<<<(n + 255) / 256, 256>>>(batch, n, b);
    k_convW2<<<(3 * D * D + 255) / 256, 256>>>(W_feat, W_t);
    k_gate<<<(n + 7) / 8, 256>>>(x, W_gate, b_gate, n);
    k_alpha<<<(b + 7) / 8, 256>>>(b);
    k_zero<<<(b * (D / 4) + 255) / 256, 256>>>(b * (D / 4));

    dim3 gm(D / 128, (n + 127) / 128);
    k_main_mma<<<gm, 512, SMEM_MAIN>>>(b_feat, n);

    k_convA<<<(b * D + 255) / 256, 256>>>(xg_old, b);

    dim3 gf(D / 128, (b + 127) / 128);
    k_final_mma<<<gf, 512, SMEM_FIN>>>(xg_old, b_t, out, b);
}

// round 15
// speedup vs baseline: 1.0462x; 1.0462x over previous
#include <cuda_runtime.h>
#include <cuda_fp16.h>
#include <math.h>
#include <stdint.h>

#define N_MAX 500000
#define B_MAX 10000
#define D 256

// ---------------- scratch (static device globals; no runtime alloc) --------
__device__ float g_gate[N_MAX];
__device__ float g_alpha[N_MAX];
__device__ int   g_batch32[N_MAX];
__device__ int   g_segstart[B_MAX + 1];
__device__ float g_xg[(size_t)B_MAX * D];
__device__ int   g_is64;
__device__ __half g_xhi[(size_t)N_MAX * D];
__device__ __half g_WhiT[D * D];                 // [n][k]
__device__ __half g_catA[(size_t)B_MAX * 2 * D]; // [g][ xg | xg_old ] fp16
__device__ __half g_WtT[2 * D * D];              // [n][k2], k2 = 512

// ---------------- helpers ----------------------------------------------------
__device__ __forceinline__ uint32_t smem_u32(const void* p) {
    uint32_t a;
    asm("{ .reg .u64 t; cvta.to.shared.u64 t, %1; cvt.u32.u64 %0, t; }"
        : "=r"(a) : "l"(p));
    return a;
}

#define LDSM_X4(r0, r1, r2, r3, addr) \
    asm volatile("ldmatrix.sync.aligned.m8n8.x4.shared.b16 {%0,%1,%2,%3}, [%4];" \
                 : "=r"(r0), "=r"(r1), "=r"(r2), "=r"(r3) : "r"(addr))

#define MMA16816(c0, c1, c2, c3, a0, a1, a2, a3, b0, b1) \
    asm volatile("mma.sync.aligned.m16n8k16.row.col.f32.f16.f16.f32 " \
                 "{%0,%1,%2,%3}, {%4,%5,%6,%7}, {%8,%9}, {%0,%1,%2,%3};" \
                 : "+f"(c0), "+f"(c1), "+f"(c2), "+f"(c3) \
                 : "r"(a0), "r"(a1), "r"(a2), "r"(a3), "r"(b0), "r"(b1))

#define CP16(dst, src) \
    asm volatile("cp.async.cg.shared.global [%0], [%1], 16;" \
                 :: "r"(dst), "l"(src) : "memory")
#define CP_COMMIT() asm volatile("cp.async.commit_group;" ::: "memory")
#define CP_WAIT(nn)  asm volatile("cp.async.wait_group %0;" :: "n"(nn) : "memory")

__device__ __forceinline__ uint32_t pack_hi2(float x, float y) {
    __half2 h = __halves2half2(__float2half_rn(x), __float2half_rn(y));
    return *(uint32_t*)&h;
}

// ---------------- dtype detection for batch (int32 vs int64) ----------------
__global__ void k_detect(const void* __restrict__ batch, int n) {
    const unsigned long long* p = (const unsigned long long*)batch;
    unsigned long long v = 0;
    int half = n / 2;
    v |= p[half - 1];
    v |= p[half / 2];
    v |= p[half / 4];
    g_is64 = (v < 0x80000000ull) ? 1 : 0;
}

// ---------------- segment boundaries from sorted batch ----------------------
__global__ void k_seg(const void* __restrict__ batch, int n, int b) {
    int i = blockIdx.x * blockDim.x + threadIdx.x;
    if (i >= n) return;
    const int is64 = g_is64;
    int bi, prev;
    if (is64) {
        bi = (int)((const long long*)batch)[i];
        prev = (i == 0) ? -1 : (int)((const long long*)batch)[i - 1];
    } else {
        bi = ((const int*)batch)[i];
        prev = (i == 0) ? -1 : ((const int*)batch)[i - 1];
    }
    if (bi < 0) bi = 0;
    if (bi > b - 1) bi = b - 1;
    if (prev < -1) prev = -1;
    if (prev > b - 1) prev = b - 1;
    g_batch32[i] = bi;
    for (int bb = prev + 1; bb <= bi; ++bb) g_segstart[bb] = i;
    if (i == n - 1) {
        for (int bb = bi + 1; bb <= b; ++bb) g_segstart[bb] = n;
    }
}

// -------- gate = x @ W_gate + b_gate, fused with x -> fp16 (16B stores) -----
__global__ void k_gate(const float* __restrict__ x, const float* __restrict__ Wg,
                       const float* __restrict__ bg, int n) {
    int warp = (blockIdx.x * blockDim.x + threadIdx.x) >> 5;
    int lane = threadIdx.x & 31;
    if (warp >= n) return;
    const float4* xr = (const float4*)(x + (size_t)warp * D);
    const float4* wr = (const float4*)Wg;
    uint4* hr = (uint4*)(g_xhi + (size_t)warp * D);
    float4 a0 = xr[2 * lane], a1 = xr[2 * lane + 1];
    float4 w0 = wr[2 * lane], w1 = wr[2 * lane + 1];
    float acc = a0.x * w0.x + a0.y * w0.y + a0.z * w0.z + a0.w * w0.w +
                a1.x * w1.x + a1.y * w1.y + a1.z * w1.z + a1.w * w1.w;
    uint4 h;
    h.x = pack_hi2(a0.x, a0.y);
    h.y = pack_hi2(a0.z, a0.w);
    h.z = pack_hi2(a1.x, a1.y);
    h.w = pack_hi2(a1.z, a1.w);
    hr[lane] = h;
#pragma unroll
    for (int o = 16; o; o >>= 1) acc += __shfl_xor_sync(0xffffffffu, acc, o);
    if (lane == 0) g_gate[warp] = acc + bg[0];
}

// ------- W_feat -> WhiT [n][k] fp16  AND  W_t -> WtT [n][k2] fp16 -----------
__global__ void k_convW2(const float* __restrict__ Wf, const float* __restrict__ Wt) {
    int t = blockIdx.x * blockDim.x + threadIdx.x;
    if (t < D * D) {
        int nn = t >> 8, kk = t & 255;
        g_WhiT[nn * D + kk] = __float2half_rn(Wf[kk * D + nn]);
    } else if (t < 3 * D * D) {
        int u = t - D * D;
        int k2 = u >> 8, nn = u & 255;
        g_WtT[nn * 2 * D + k2] = __float2half_rn(Wt[k2 * D + nn]);
    }
}

// ---------------- [xg | xg_old] -> fp16 packed A ----------------------------
__global__ void k_convA(const float* __restrict__ xg_old, int b) {
    int t = blockIdx.x * blockDim.x + threadIdx.x;
    if (t >= b * D) return;
    int g = t >> 8, c = t & 255;
    g_catA[(size_t)g * 512 + c]       = __float2half_rn(g_xg[(size_t)g * D + c]);
    g_catA[(size_t)g * 512 + 256 + c] = __float2half_rn(xg_old[(size_t)g * D + c]);
}

// ---------------- per-graph softmax weights (warp per graph) ----------------
__global__ void k_alpha(int b) {
    int w = (blockIdx.x * blockDim.x + threadIdx.x) >> 5;
    int lane = threadIdx.x & 31;
    if (w >= b) return;
    int s = g_segstart[w], e = g_segstart[w + 1];
    if (s >= e) return;
    float m = -1e30f;
    for (int i = s + lane; i < e; i += 32) m = fmaxf(m, g_gate[i]);
#pragma unroll
    for (int o = 16; o; o >>= 1) m = fmaxf(m, __shfl_xor_sync(0xffffffffu, m, o));
    float sum = 0.f;
    for (int i = s + lane; i < e; i += 32) sum += expf(g_gate[i] - m);
#pragma unroll
    for (int o = 16; o; o >>= 1) sum += __shfl_xor_sync(0xffffffffu, sum, o);
    float inv = 1.0f / sum;
    for (int i = s + lane; i < e; i += 32) g_alpha[i] = expf(g_gate[i] - m) * inv;
}

// ---------------- zero xg accumulator ---------------------------------------
__global__ void k_zero(int total4) {
    int i = blockIdx.x * blockDim.x + threadIdx.x;
    if (i < total4) ((float4*)g_xg)[i] = make_float4(0.f, 0.f, 0.f, 0.f);
}

// ========= single-term fp16 GEMM: xg += alpha * lrelu(xhi @ Whi + b) ========
// CTA 128x128, 512 threads, 2 CTAs/SM. B (Whi, full K=256) resident in smem.
// A (xhi) streamed in 4 chunks of K=64 through 2 cp.async stages. (R13 form)
#define LDKB 144     // A row stride bytes (64 halfs + pad)
#define LDNB 528     // B row stride bytes (256 halfs + pad)
#define OFF_BHI 0
#define OFF_A0  67584
#define A_STAGE 18432
#define OFF_BATCH 104448
#define OFF_ALPHA 104960
#define OFF_BIAS  105472
#define SMEM_MAIN 105984
#define SD_STRIDE 130

__global__ void __launch_bounds__(512, 2)
k_main_mma(const float* __restrict__ bf, int n) {
    extern __shared__ char smem[];
    const int tid = threadIdx.x;
    const int m0 = blockIdx.y * 128;
    const int n0 = blockIdx.x * 128;
    const uint32_t sbase = smem_u32(smem);
    int*   sBatch = (int*)(smem + OFF_BATCH);
    float* sAlpha = (float*)(smem + OFF_ALPHA);
    float* sBias  = (float*)(smem + OFF_BIAS);
    float* sD     = (float*)smem;

    if (tid < 128) {
        int r = m0 + tid;
        sBatch[tid] = (r < n) ? g_batch32[r] : -1;
        sBias[tid]  = bf[n0 + tid];
    } else if (tid < 256) {
        int r = m0 + tid - 128;
        sAlpha[tid - 128] = (r < n) ? g_alpha[r] : 0.f;
    }

    const int crow = tid >> 2;
    const int cseg = tid & 3;
    const char* whiT = (const char*)g_WhiT;
    const char* xhi  = (const char*)g_xhi;

    {
        const size_t bsrc = ((size_t)(n0 + crow)) * 512;
        const uint32_t bdst = sbase + crow * LDNB;
#pragma unroll
        for (int j = 0; j < 8; j++) {
            int s = cseg + 4 * j;
            CP16(bdst + OFF_BHI + s * 16, whiT + bsrc + s * 16);
        }
    }
    const bool avalid = (m0 + crow) < n;
    const size_t asrc_row = ((size_t)(m0 + (avalid ? crow : 0))) * 512;

#pragma unroll
    for (int st = 0; st < 2; st++) {
        const uint32_t adst = sbase + OFF_A0 + st * A_STAGE + crow * LDKB;
        const size_t asrc = asrc_row + st * 128;
        if (avalid) {
#pragma unroll
            for (int j = 0; j < 2; j++) {
                int s = cseg + 4 * j;
                CP16(adst + s * 16, xhi + asrc + s * 16);
            }
        } else {
#pragma unroll
            for (int j = 0; j < 2; j++) {
                int s = cseg + 4 * j;
                asm volatile("st.shared.v4.b32 [%0], {%1,%1,%1,%1};"
                             :: "r"(adst + s * 16), "r"(0u));
            }
        }
        CP_COMMIT();
    }
    CP_WAIT(1);
    __syncthreads();

    const int wid = tid >> 5, lane = tid & 31;
    const int wm = wid >> 2, wn = wid & 3;
    const uint32_t a_off = (uint32_t)((wm * 32 + (lane & 15)) * LDKB + ((lane >> 4) << 4));
    const uint32_t b_off = (uint32_t)((wn * 32 + (lane & 15)) * LDNB + ((lane >> 4) << 4));

    float c[2][4][4];
#pragma unroll
    for (int mi = 0; mi < 2; mi++)
#pragma unroll
        for (int nt = 0; nt < 4; nt++)
#pragma unroll
            for (int q = 0; q < 4; q++) c[mi][nt][q] = 0.f;

    for (int ch = 0; ch < 4; ch++) {
        const int st = ch & 1;
        const uint32_t aH = sbase + OFF_A0 + st * A_STAGE + a_off;
        const uint32_t bH = sbase + OFF_BHI + b_off + (uint32_t)(ch * 128);
#pragma unroll
        for (int ks = 0; ks < 4; ks++) {
            const uint32_t koff = (uint32_t)(ks * 32);
            uint32_t ah[2][4], bh[2][4];
#pragma unroll
            for (int mi = 0; mi < 2; mi++) {
                uint32_t adr = aH + (uint32_t)(mi * 16 * LDKB) + koff;
                LDSM_X4(ah[mi][0], ah[mi][1], ah[mi][2], ah[mi][3], adr);
            }
#pragma unroll
            for (int np = 0; np < 2; np++) {
                uint32_t adr = bH + (uint32_t)(np * 16 * LDNB) + koff;
                LDSM_X4(bh[np][0], bh[np][1], bh[np][2], bh[np][3], adr);
            }
#pragma unroll
            for (int mi = 0; mi < 2; mi++)
#pragma unroll
                for (int np = 0; np < 2; np++)
#pragma unroll
                    for (int t = 0; t < 2; t++) {
                        float* cc = c[mi][np * 2 + t];
                        MMA16816(cc[0], cc[1], cc[2], cc[3],
                                 ah[mi][0], ah[mi][1], ah[mi][2], ah[mi][3],
                                 bh[np][t], bh[np][t + 2]);
                    }
        }
        __syncthreads();

        if (ch + 2 < 4) {
            const uint32_t adst = sbase + OFF_A0 + st * A_STAGE + crow * LDKB;
            const size_t asrc = asrc_row + (ch + 2) * 128;
            if (avalid) {
#pragma unroll
                for (int j = 0; j < 2; j++) {
                    int s = cseg + 4 * j;
                    CP16(adst + s * 16, xhi + asrc + s * 16);
                }
            }
            CP_COMMIT();
        }
        if (ch == 0 || ch == 1) {
            CP_WAIT(1);
            __syncthreads();
        } else if (ch == 2) {
            CP_WAIT(0);
            __syncthreads();
        }
    }

#pragma unroll
    for (int mi = 0; mi < 2; mi++) {
        const int r0 = wm * 32 + mi * 16 + (lane >> 2);
        const int r1 = r0 + 8;
        const float al0 = sAlpha[r0], al1 = sAlpha[r1];
#pragma unroll
        for (int nt = 0; nt < 4; nt++) {
            const int col = wn * 32 + nt * 8 + (lane & 3) * 2;
            const float b0 = sBias[col], b1 = sBias[col + 1];
            float v0 = c[mi][nt][0] + b0, v1 = c[mi][nt][1] + b1;
            float v2 = c[mi][nt][2] + b0, v3 = c[mi][nt][3] + b1;
            v0 = (v0 >= 0.f) ? v0 : 0.01f * v0;
            v1 = (v1 >= 0.f) ? v1 : 0.01f * v1;
            v2 = (v2 >= 0.f) ? v2 : 0.01f * v2;
            v3 = (v3 >= 0.f) ? v3 : 0.01f * v3;
            *(float2*)&sD[r0 * SD_STRIDE + col] = make_float2(v0 * al0, v1 * al0);
            *(float2*)&sD[r1 * SD_STRIDE + col] = make_float2(v2 * al1, v3 * al1);
        }
    }
    __syncthreads();

    {
        const int col = tid & 127, q = tid >> 7;
        const int rbeg = q * 32;
        float sum = 0.f;
        int prevb = -2;
        for (int r = 0; r < 32; r++) {
            int rr = rbeg + r;
            int b = sBatch[rr];
            if (b != prevb) {
                if (prevb >= 0)
                    atomicAdd(&g_xg[(size_t)prevb * D + n0 + col], sum);
                sum = 0.f;
                prevb = b;
            }
            if (b >= 0) sum += sD[rr * SD_STRIDE + col];
        }
        if (prevb >= 0) atomicAdd(&g_xg[(size_t)prevb * D + n0 + col], sum);
    }
}

// ===== fp16 final GEMM: out = lrelu([xg|xg_old] @ W_t + b_t) + xg_old =======
// CTA 128x128, 512 threads, 2 CTAs/SM. A+B tiles stream together in 2 stages;
// 8 chunks cover K2=512. (R14 form — single-wave grid benefits from no prologue)
#define F_TILE_B 18432
#define F_STG_B  36864
#define F_OFF_BIAS 73728
#define SMEM_FIN   74240

__global__ void __launch_bounds__(512, 2)
k_final_mma(const float* __restrict__ xg_old, const float* __restrict__ bt,
            float* __restrict__ out, int bsz) {
    extern __shared__ char smem[];
    const int tid = threadIdx.x;
    const int m0 = blockIdx.y * 128;
    const int n0 = blockIdx.x * 128;
    const uint32_t sbase = smem_u32(smem);
    float* sBias = (float*)(smem + F_OFF_BIAS);

    if (tid < 128) sBias[tid] = bt[n0 + tid];

    const int crow = tid >> 2;
    const int cseg = tid & 3;
    const char* wt  = (const char*)g_WtT;
    const char* cat = (const char*)g_catA;

    const bool avalid = (m0 + crow) < bsz;
    const size_t asrc_row = ((size_t)(m0 + (avalid ? crow : 0))) * 1024;
    const size_t bsrc_row = ((size_t)(n0 + crow)) * 1024;
    const uint32_t cdstA = sbase + crow * LDKB;
    const uint32_t cdstB = sbase + F_TILE_B + crow * LDKB;

    auto fill = [&](int st, int ch) {
        const uint32_t so = (uint32_t)(st * F_STG_B);
        const size_t ko = (size_t)(ch * 128);
        if (avalid) {
#pragma unroll
            for (int j = 0; j < 2; j++) {
                int s = cseg + 4 * j;
                CP16(cdstA + so + s * 16, cat + asrc_row + ko + s * 16);
            }
        } else {
#pragma unroll
            for (int j = 0; j < 2; j++) {
                int s = cseg + 4 * j;
                asm volatile("st.shared.v4.b32 [%0], {%1,%1,%1,%1};"
                             :: "r"(cdstA + so + s * 16), "r"(0u));
            }
        }
#pragma unroll
        for (int j = 0; j < 2; j++) {
            int s = cseg + 4 * j;
            CP16(cdstB + so + s * 16, wt + bsrc_row + ko + s * 16);
        }
        CP_COMMIT();
    };

    fill(0, 0);
    fill(1, 1);
    CP_WAIT(1);
    __syncthreads();

    const int wid = tid >> 5, lane = tid & 31;
    const int wm = wid >> 2, wn = wid & 3;
    const uint32_t a_off = (uint32_t)((wm * 32 + (lane & 15)) * LDKB + ((lane >> 4) << 4));
    const uint32_t b_off = (uint32_t)((wn * 32 + (lane & 15)) * LDKB + ((lane >> 4) << 4)) + F_TILE_B;

    float c[2][4][4];
#pragma unroll
    for (int mi = 0; mi < 2; mi++)
#pragma unroll
        for (int nt = 0; nt < 4; nt++)
#pragma unroll
            for (int q = 0; q < 4; q++) c[mi][nt][q] = 0.f;

    for (int ch = 0; ch < 8; ch++) {
        const int st = ch & 1;
        const uint32_t aH = sbase + (uint32_t)(st * F_STG_B) + a_off;
        const uint32_t bH = sbase + (uint32_t)(st * F_STG_B) + b_off;
#pragma unroll
        for (int ks = 0; ks < 4; ks++) {
            const uint32_t koff = (uint32_t)(ks * 32);
            uint32_t ah[2][4], bh[2][4];
#pragma unroll
            for (int mi = 0; mi < 2; mi++) {
                uint32_t adr = aH + (uint32_t)(mi * 16 * LDKB) + koff;
                LDSM_X4(ah[mi][0], ah[mi][1], ah[mi][2], ah[mi][3], adr);
            }
#pragma unroll
            for (int np = 0; np < 2; np++) {
                uint32_t adr = bH + (uint32_t)(np * 16 * LDKB) + koff;
                LDSM_X4(bh[np][0], bh[np][1], bh[np][2], bh[np][3], adr);
            }
#pragma unroll
            for (int mi = 0; mi < 2; mi++)
#pragma unroll
                for (int np = 0; np < 2; np++)
#pragma unroll
                    for (int t = 0; t < 2; t++) {
                        float* cc = c[mi][np * 2 + t];
                        MMA16816(cc[0], cc[1], cc[2], cc[3],
                                 ah[mi][0], ah[mi][1], ah[mi][2], ah[mi][3],
                                 bh[np][t], bh[np][t + 2]);
                    }
        }
        __syncthreads();

        if (ch + 2 < 8) fill(st, ch + 2);
        if (ch < 6) {
            CP_WAIT(1);
            __syncthreads();
        } else if (ch == 6) {
            CP_WAIT(0);
            __syncthreads();
        }
    }

#pragma unroll
    for (int mi = 0; mi < 2; mi++) {
        const int r0 = wm * 32 + mi * 16 + (lane >> 2);
        const int r1 = r0 + 8;
#pragma unroll
        for (int nt = 0; nt < 4; nt++) {
            const int col = wn * 32 + nt * 8 + (lane & 3) * 2;
            const float b0 = sBias[col], b1 = sBias[col + 1];
            int g0 = m0 + r0, g1 = m0 + r1;
            if (g0 < bsz) {
                float2 res = *(const float2*)(xg_old + (size_t)g0 * D + n0 + col);
                float v0 = c[mi][nt][0] + b0, v1 = c[mi][nt][1] + b1;
                v0 = (v0 >= 0.f) ? v0 : 0.01f * v0;
                v1 = (v1 >= 0.f) ? v1 : 0.01f * v1;
                *(float2*)(out + (size_t)g0 * D + n0 + col) =
                    make_float2(v0 + res.x, v1 + res.y);
            }
            if (g1 < bsz) {
                float2 res = *(const float2*)(xg_old + (size_t)g1 * D + n0 + col);
                float v2 = c[mi][nt][2] + b0, v3 = c[mi][nt][3] + b1;
                v2 = (v2 >= 0.f) ? v2 : 0.01f * v2;
                v3 = (v3 >= 0.f) ? v3 : 0.01f * v3;
                *(float2*)(out + (size_t)g1 * D + n0 + col) =
                    make_float2(v2 + res.x, v3 + res.y);
            }
        }
    }
}

// ---------------- launcher ---------------------------------------------------
extern "C" void kernel_launch(void* const* d_in, const int* in_sizes, int n_in,
                              void* d_out, int out_size) {
    const float* xg_old = (const float*)d_in[0];
    const float* x      = (const float*)d_in[1];
    const void*  batch  = d_in[2];
    const float* W_gate = (const float*)d_in[3];
    const float* b_gate = (const float*)d_in[4];
    const float* W_feat = (const float*)d_in[5];
    const float* b_feat = (const float*)d_in[6];
    const float* W_t    = (const float*)d_in[7];
    const float* b_t    = (const float*)d_in[8];
    float*       out    = (float*)d_out;

    int n = in_sizes[2];
    int b = in_sizes[0] / D;
    if (n > N_MAX) n = N_MAX;
    if (b > B_MAX) b = B_MAX;

    cudaFuncSetAttribute(k_main_mma, cudaFuncAttributeMaxDynamicSharedMemorySize,
                         SMEM_MAIN);
    cudaFuncSetAttribute(k_final_mma, cudaFuncAttributeMaxDynamicSharedMemorySize,
                         SMEM_FIN);

    k_detect<<<1, 1>>>(batch, n);
    k_seg<<<(n + 255) / 256, 256>>>(batch, n, b);
    k_convW2<<<(3 * D * D + 255) / 256, 256>>>(W_feat, W_t);
    k_gate<<<(n + 7) / 8, 256>>>(x, W_gate, b_gate, n);
    k_alpha<<<(b + 7) / 8, 256>>>(b);
    k_zero<<<(b * (D / 4) + 255) / 256, 256>>>(b * (D / 4));

    dim3 gm(D / 128, (n + 127) / 128);
    k_main_mma<<<gm, 512, SMEM_MAIN>>>(b_feat, n);

    k_convA<<<(b * D + 255) / 256, 256>>>(xg_old, b);

    dim3 gf(D / 128, (b + 127) / 128);
    k_final_mma<<<gf, 512, SMEM_FIN>>>(xg_old, b_t, out, b);
}